// round 2
// baseline (speedup 1.0000x reference)
#include <cuda_runtime.h>

// ---------------------------------------------------------------------------
// UpsampleUpdatingModel2: fp32 baseline
//   24 images, 256 ch, 56x56. Heavy work = 6x conv3x3 256->256 (direct conv,
//   register-blocked 8oc x 7px per thread, FMA-bound) + 1x1 conv + gathers.
// ---------------------------------------------------------------------------

#define N_IMG 24
#define CH    256
#define HH    56
#define WW    56
#define HWP   3136              // 56*56

// Scratch (allocation-free rule: __device__ globals)
__device__ float g_pm [N_IMG * 2 * HWP];
__device__ float g_bufA[N_IMG * CH * HWP];
__device__ float g_bufB[N_IMG * CH * HWP];
__device__ float g_bufC[N_IMG * CH * HWP];

static inline int cdiv(int a, int b) { return (a + b - 1) / b; }

// ---------------------------------------------------------------------------
// 1) resize_bilinear 112->56 with scale=2 is an exact 2x2 average; then *0.25.
// ---------------------------------------------------------------------------
__global__ void downsample_k(const float* __restrict__ src, float* __restrict__ dst) {
    int idx = blockIdx.x * 256 + threadIdx.x;
    if (idx >= 48 * HWP) return;                 // 24*2 channels of 56x56
    int nc = idx / HWP, p = idx - nc * HWP;
    int i = p / WW, j = p - i * WW;
    const float* s = src + (size_t)nc * 112 * 112;
    int base = (2 * i) * 112 + 2 * j;
    float v = s[base] + s[base + 1] + s[base + 112] + s[base + 113];
    dst[idx] = v * 0.0625f;                      // (avg of 4) * 0.25 scale
}

// ---------------------------------------------------------------------------
// 2) conv3x3 2->256 + bias + relu (tiny K, one thread per output element)
// ---------------------------------------------------------------------------
__global__ void conv_first_k(const float* __restrict__ pm, const float* __restrict__ wt,
                             const float* __restrict__ bias, float* __restrict__ out) {
    int idx = blockIdx.x * 256 + threadIdx.x;
    if (idx >= N_IMG * CH * HWP) return;
    int p = idx % HWP;
    int o = (idx / HWP) & (CH - 1);
    int n = idx / (CH * HWP);
    int i = p / WW, j = p - (p / WW) * WW;
    float s = bias[o];
    #pragma unroll
    for (int c = 0; c < 2; c++) {
        const float* pc = pm + (size_t)(n * 2 + c) * HWP;
        const float* wc = wt + (size_t)(o * 2 + c) * 9;
        #pragma unroll
        for (int dy = 0; dy < 3; dy++) {
            int y = i + dy - 1;
            if ((unsigned)y >= (unsigned)HH) continue;
            #pragma unroll
            for (int dx = 0; dx < 3; dx++) {
                int x = j + dx - 1;
                if ((unsigned)x >= (unsigned)WW) continue;
                s = fmaf(wc[dy * 3 + dx], pc[y * WW + x], s);
            }
        }
    }
    out[idx] = fmaxf(s, 0.f);
}

// ---------------------------------------------------------------------------
// 3) deformable 1x1 bilinear sample (zero outside), feat[n] = i_features[n/3]
//    One thread handles 8 channels of one pixel (corner math computed once).
// ---------------------------------------------------------------------------
__global__ void deform_k(const float* __restrict__ feat, const float* __restrict__ pm,
                         float* __restrict__ out) {
    int idx = blockIdx.x * 256 + threadIdx.x;
    if (idx >= N_IMG * 32 * HWP) return;
    int p  = idx % HWP;
    int cg = (idx / HWP) & 31;
    int n  = idx / (32 * HWP);
    int i = p / WW, j = p - (p / WW) * WW;

    float dy = pm[(size_t)(n * 2 + 0) * HWP + p];
    float dx = pm[(size_t)(n * 2 + 1) * HWP + p];
    float gy = (float)i + dy, gx = (float)j + dx;
    float fy = floorf(gy), fx = floorf(gx);
    float ty = gy - fy, tx = gx - fx;
    int y0 = (int)fy, x0 = (int)fx;
    int y1 = y0 + 1, x1 = x0 + 1;
    bool vy0 = (unsigned)y0 < (unsigned)HH, vy1 = (unsigned)y1 < (unsigned)HH;
    bool vx0 = (unsigned)x0 < (unsigned)WW, vx1 = (unsigned)x1 < (unsigned)WW;
    float w00 = (vy0 && vx0) ? (1.f - ty) * (1.f - tx) : 0.f;
    float w01 = (vy0 && vx1) ? (1.f - ty) * tx         : 0.f;
    float w10 = (vy1 && vx0) ? ty * (1.f - tx)         : 0.f;
    float w11 = (vy1 && vx1) ? ty * tx                 : 0.f;
    int y0c = min(max(y0, 0), HH - 1), y1c = min(max(y1, 0), HH - 1);
    int x0c = min(max(x0, 0), WW - 1), x1c = min(max(x1, 0), WW - 1);
    int i00 = y0c * WW + x0c, i01 = y0c * WW + x1c;
    int i10 = y1c * WW + x0c, i11 = y1c * WW + x1c;

    const float* f = feat + ((size_t)(n / 3) * CH + cg * 8) * HWP;
    float* o = out + ((size_t)n * CH + cg * 8) * HWP + p;
    #pragma unroll
    for (int c = 0; c < 8; c++) {
        const float* fc = f + (size_t)c * HWP;
        o[(size_t)c * HWP] = w00 * fc[i00] + w01 * fc[i01] + w10 * fc[i10] + w11 * fc[i11];
    }
}

// ---------------------------------------------------------------------------
// 4) conv3x3 256->256 (the workhorse).
//    Block: n x (64 oc) x (4 rows, full 56 width). 256 threads.
//    Thread: 8 oc x 7 px register tile. Smem-chunked over 8 input channels.
//    FMA:LDS ~ 5.1 -> FMA-pipe bound.
// ---------------------------------------------------------------------------
template <bool RELU, bool ADD_EXTRA>
__global__ __launch_bounds__(256, 2)
void conv3x3_k(const float* __restrict__ in, const float* __restrict__ wt,
               const float* __restrict__ bias, const float* __restrict__ extra,
               float* __restrict__ out) {
    __shared__ float sIn[8][6][58];
    __shared__ float sW[64][72];

    const int tid = threadIdx.x;
    const int n = blockIdx.z, ocb = blockIdx.y, rb = blockIdx.x;
    const int oc_sub = tid >> 5;          // 0..7
    const int s      = tid & 31;
    const int row    = s >> 3;            // 0..3
    const int colb   = (s & 7) * 7;       // 0..49 step 7

    float acc[8][7];
    #pragma unroll
    for (int k = 0; k < 8; k++)
        #pragma unroll
        for (int c = 0; c < 7; c++) acc[k][c] = 0.f;

    const int r0 = rb * 4 - 1;
    const float* inN = in + (size_t)n * CH * HWP;
    const float* wtB = wt + (size_t)(ocb * 64) * (CH * 9);

    for (int ic0 = 0; ic0 < CH; ic0 += 8) {
        __syncthreads();
        // input tile: 8ch x 6rows x 58cols with zero halo
        for (int idx = tid; idx < 8 * 6 * 58; idx += 256) {
            int ch  = idx / 348;
            int rem = idx - ch * 348;
            int r   = rem / 58;
            int cc  = rem - r * 58;
            int gr = r0 + r, gc = cc - 1;
            float v = 0.f;
            if ((unsigned)gr < (unsigned)HH && (unsigned)gc < (unsigned)WW)
                v = inN[(size_t)(ic0 + ch) * HWP + gr * WW + gc];
            sIn[ch][r][cc] = v;
        }
        // weights: 64oc x 8ic x 9tap
        for (int idx = tid; idx < 64 * 72; idx += 256) {
            int oc  = idx / 72;
            int rem = idx - oc * 72;
            sW[oc][rem] = wtB[(size_t)oc * (CH * 9) + ic0 * 9 + rem];
        }
        __syncthreads();

        for (int ic = 0; ic < 8; ic++) {
            #pragma unroll
            for (int dy = 0; dy < 3; dy++) {
                float xr[9];
                #pragma unroll
                for (int cc = 0; cc < 9; cc++) xr[cc] = sIn[ic][row + dy][colb + cc];
                #pragma unroll
                for (int dx = 0; dx < 3; dx++) {
                    float w[8];
                    #pragma unroll
                    for (int k = 0; k < 8; k++) w[k] = sW[oc_sub * 8 + k][ic * 9 + dy * 3 + dx];
                    #pragma unroll
                    for (int k = 0; k < 8; k++)
                        #pragma unroll
                        for (int c = 0; c < 7; c++)
                            acc[k][c] = fmaf(w[k], xr[c + dx], acc[k][c]);
                }
            }
        }
    }

    const int orow = rb * 4 + row;
    #pragma unroll
    for (int k = 0; k < 8; k++) {
        int oc = ocb * 64 + oc_sub * 8 + k;
        float b = bias[oc];
        size_t off = ((size_t)n * CH + oc) * HWP + orow * WW + colb;
        float* o = out + off;
        #pragma unroll
        for (int c = 0; c < 7; c++) {
            float v = acc[k][c] + b;
            if (RELU) v = fmaxf(v, 0.f);
            if (ADD_EXTRA) v += extra[off + c];
            o[c] = v;
        }
    }
}

// ---------------------------------------------------------------------------
// 5) 1x1 conv 256->256 (+bias, no relu): pf = dw @ sampled + db
// ---------------------------------------------------------------------------
__global__ __launch_bounds__(256, 2)
void conv1x1_k(const float* __restrict__ in, const float* __restrict__ wt,
               const float* __restrict__ bias, float* __restrict__ out) {
    __shared__ float sIn[8][224];
    __shared__ float sW[64][8];

    const int tid = threadIdx.x;
    const int n = blockIdx.z, ocb = blockIdx.y, rb = blockIdx.x;
    const int oc_sub = tid >> 5;
    const int s      = tid & 31;
    const int row    = s >> 3;
    const int colb   = (s & 7) * 7;

    float acc[8][7];
    #pragma unroll
    for (int k = 0; k < 8; k++)
        #pragma unroll
        for (int c = 0; c < 7; c++) acc[k][c] = 0.f;

    const float* inN = in + (size_t)n * CH * HWP + rb * 4 * WW;

    for (int ic0 = 0; ic0 < CH; ic0 += 8) {
        __syncthreads();
        for (int idx = tid; idx < 8 * 224; idx += 256) {
            int ch = idx / 224, px = idx - (idx / 224) * 224;
            sIn[ch][px] = inN[(size_t)(ic0 + ch) * HWP + px];
        }
        for (int idx = tid; idx < 64 * 8; idx += 256) {
            int oc = idx >> 3, ic = idx & 7;
            sW[oc][ic] = wt[(size_t)(ocb * 64 + oc) * CH + ic0 + ic];
        }
        __syncthreads();
        #pragma unroll
        for (int ic = 0; ic < 8; ic++) {
            float w[8], x[7];
            #pragma unroll
            for (int k = 0; k < 8; k++) w[k] = sW[oc_sub * 8 + k][ic];
            #pragma unroll
            for (int c = 0; c < 7; c++) x[c] = sIn[ic][row * WW + colb + c];
            #pragma unroll
            for (int k = 0; k < 8; k++)
                #pragma unroll
                for (int c = 0; c < 7; c++)
                    acc[k][c] = fmaf(w[k], x[c], acc[k][c]);
        }
    }

    #pragma unroll
    for (int k = 0; k < 8; k++) {
        int oc = ocb * 64 + oc_sub * 8 + k;
        float b = bias[oc];
        float* o = out + ((size_t)n * CH + oc) * HWP + (rb * 4 + row) * WW + colb;
        #pragma unroll
        for (int c = 0; c < 7; c++) o[c] = acc[k][c] + b;
    }
}

// ---------------------------------------------------------------------------
// 6) spatial mean pool: pooled[n*256+c] = mean_{hw} p2d[n,c,:,:]
// ---------------------------------------------------------------------------
__global__ void pool_k(const float* __restrict__ p2d, float* __restrict__ pooled) {
    int nc = blockIdx.x;
    const float* src = p2d + (size_t)nc * HWP;
    float s = 0.f;
    for (int i = threadIdx.x; i < HWP; i += 256) s += src[i];
    #pragma unroll
    for (int o = 16; o > 0; o >>= 1) s += __shfl_xor_sync(0xffffffffu, s, o);
    __shared__ float sm[8];
    if ((threadIdx.x & 31) == 0) sm[threadIdx.x >> 5] = s;
    __syncthreads();
    if (threadIdx.x < 8) {
        s = sm[threadIdx.x];
        #pragma unroll
        for (int o = 4; o > 0; o >>= 1) s += __shfl_xor_sync(0xffu, s, o);
        if (threadIdx.x == 0) pooled[nc] = s * (1.f / (float)HWP);
    }
}

// ---------------------------------------------------------------------------
extern "C" void kernel_launch(void* const* d_in, const int* in_sizes, int n_in,
                              void* d_out, int out_size) {
    // metadata order: imgs, i_features, p_motions, dw, db, mw1, mb1, mw2, mb2,
    //                 mw3, mb3, ew1, eb1, ew2, eb2, ew3, eb3, ew4, eb4
    const float* i_features = (const float*)d_in[1];
    const float* p_motions  = (const float*)d_in[2];
    const float* dw  = (const float*)d_in[3];
    const float* db  = (const float*)d_in[4];
    const float* mw1 = (const float*)d_in[5];
    const float* mb1 = (const float*)d_in[6];
    const float* mw2 = (const float*)d_in[7];
    const float* mb2 = (const float*)d_in[8];
    const float* mw3 = (const float*)d_in[9];
    const float* mb3 = (const float*)d_in[10];
    const float* ew1 = (const float*)d_in[11];
    const float* eb1 = (const float*)d_in[12];
    const float* ew2 = (const float*)d_in[13];
    const float* eb2 = (const float*)d_in[14];
    const float* ew3 = (const float*)d_in[15];
    const float* eb3 = (const float*)d_in[16];
    const float* ew4 = (const float*)d_in[17];
    const float* eb4 = (const float*)d_in[18];
    float* out = (float*)d_out;

    float *pm, *bA, *bB, *bC;
    cudaGetSymbolAddress((void**)&pm, g_pm);
    cudaGetSymbolAddress((void**)&bA, g_bufA);
    cudaGetSymbolAddress((void**)&bB, g_bufB);
    cudaGetSymbolAddress((void**)&bC, g_bufC);

    float* p2d    = out + 6144;   // output = [pooled (2*4*3*256), p2d (24*256*56*56)]
    float* pooled = out;

    dim3 g(14, 4, 24);            // (row tiles, oc tiles, images)

    // motion downsample
    downsample_k<<<cdiv(48 * HWP, 256), 256>>>(p_motions, pm);

    // emb chain: pm -> A -> B -> A -> C   (C = emb)
    conv_first_k<<<cdiv(N_IMG * CH * HWP, 256), 256>>>(pm, ew1, eb1, bA);
    conv3x3_k<true, false><<<g, 256>>>(bA, ew2, eb2, nullptr, bB);
    conv3x3_k<true, false><<<g, 256>>>(bB, ew3, eb3, nullptr, bA);
    conv3x3_k<true, false><<<g, 256>>>(bA, ew4, eb4, nullptr, bC);

    // deform sample -> A ; 1x1 conv -> B ; pf chain B -> A -> B ; final + emb -> p2d
    deform_k<<<cdiv(N_IMG * 32 * HWP, 256), 256>>>(i_features, pm, bA);
    conv1x1_k<<<g, 256>>>(bA, dw, db, bB);
    conv3x3_k<true, false><<<g, 256>>>(bB, mw1, mb1, nullptr, bA);
    conv3x3_k<true, false><<<g, 256>>>(bA, mw2, mb2, nullptr, bB);
    conv3x3_k<true, true><<<g, 256>>>(bB, mw3, mb3, bC, p2d);

    // pooled
    pool_k<<<N_IMG * CH, 256>>>(p2d, pooled);
}

// round 5
// speedup vs baseline: 2.6059x; 2.6059x over previous
#include <cuda_runtime.h>
#include <cuda_bf16.h>
#include <cstdint>

// ---------------------------------------------------------------------------
// UpsampleUpdatingModel2 — split-bf16 implicit-GEMM convs on mma.sync (HMMA)
// (tcgen05 unavailable: harness lowers via compute_103, arch-specific ops rejected)
// ---------------------------------------------------------------------------

#define N_IMG 24
#define CH    256
#define HH    56
#define WW    56
#define HWP   3136
#define PW    58          // padded row width (1 zero col each side)
#define PHWP  3248        // 56*58 padded pixels per image

// Scratch (__device__ globals: allocation-free rule)
__device__ __align__(128) float g_pm  [N_IMG * 2 * HWP];
__device__ __align__(128) float g_bufA[N_IMG * CH * HWP];
__device__ __align__(128) float g_bufB[N_IMG * CH * HWP];
__device__ __align__(128) float g_bufC[N_IMG * CH * HWP];
__device__ __align__(128) __nv_bfloat16 g_xt_hi[N_IMG * PHWP * CH];
__device__ __align__(128) __nv_bfloat16 g_xt_lo[N_IMG * PHWP * CH];
__device__ __align__(128) __nv_bfloat16 g_wA_hi[9 * CH * CH];   // [tap][oc][ic]
__device__ __align__(128) __nv_bfloat16 g_wA_lo[9 * CH * CH];

static inline int cdiv(int a, int b) { return (a + b - 1) / b; }

// ------------------------------ PTX helpers --------------------------------
__device__ __forceinline__ uint32_t smem_u32(const void* p) {
    uint32_t a;
    asm("{ .reg .u64 t; cvta.to.shared.u64 t, %1; cvt.u32.u64 %0, t; }" : "=r"(a) : "l"(p));
    return a;
}
__device__ __forceinline__ void ldsm_x4(uint32_t* r, uint32_t addr) {
    asm volatile("ldmatrix.sync.aligned.m8n8.x4.shared.b16 {%0,%1,%2,%3}, [%4];"
                 : "=r"(r[0]), "=r"(r[1]), "=r"(r[2]), "=r"(r[3]) : "r"(addr));
}
__device__ __forceinline__ void ldsm_x2(uint32_t* r, uint32_t addr) {
    asm volatile("ldmatrix.sync.aligned.m8n8.x2.shared.b16 {%0,%1}, [%2];"
                 : "=r"(r[0]), "=r"(r[1]) : "r"(addr));
}
__device__ __forceinline__ void mma16816(float* d, const uint32_t* a, const uint32_t* b) {
    asm volatile(
        "mma.sync.aligned.m16n8k16.row.col.f32.bf16.bf16.f32 "
        "{%0,%1,%2,%3}, {%4,%5,%6,%7}, {%8,%9}, {%0,%1,%2,%3};"
        : "+f"(d[0]), "+f"(d[1]), "+f"(d[2]), "+f"(d[3])
        : "r"(a[0]), "r"(a[1]), "r"(a[2]), "r"(a[3]), "r"(b[0]), "r"(b[1]));
}

// SMEM layout: K-major tiles, 64 ic per stage, row stride 144B (ldmatrix
// conflict-free: bank group = 4*row mod 32).
#define RS     144
#define SM_AHI 0                       // 128 rows * 144B = 18432
#define SM_ALO (SM_AHI + 128 * RS)
#define SM_BHI (SM_ALO + 128 * RS)     // 112 rows * 144B = 16128
#define SM_BLO (SM_BHI + 112 * RS)
#define SM_TOT (SM_BLO + 112 * RS)     // 69120 bytes

// ---------------------------------------------------------------------------
// downsample: bilinear 112->56 (exact 2x2 avg) * 0.25 scale
// ---------------------------------------------------------------------------
__global__ void downsample_k(const float* __restrict__ src, float* __restrict__ dst) {
    int idx = blockIdx.x * 256 + threadIdx.x;
    if (idx >= 48 * HWP) return;
    int nc = idx / HWP, p = idx - nc * HWP;
    int i = p / WW, j = p - i * WW;
    const float* s = src + (size_t)nc * 112 * 112;
    int base = (2 * i) * 112 + 2 * j;
    dst[idx] = (s[base] + s[base + 1] + s[base + 112] + s[base + 113]) * 0.0625f;
}

// ---------------------------------------------------------------------------
// conv3x3 2->256 + relu (tiny K, FFMA fine)
// ---------------------------------------------------------------------------
__global__ void conv_first_k(const float* __restrict__ pm, const float* __restrict__ wt,
                             const float* __restrict__ bias, float* __restrict__ out) {
    int idx = blockIdx.x * 256 + threadIdx.x;
    if (idx >= N_IMG * CH * HWP) return;
    int p = idx % HWP;
    int o = (idx / HWP) & (CH - 1);
    int n = idx / (CH * HWP);
    int i = p / WW, j = p - (p / WW) * WW;
    float s = bias[o];
    #pragma unroll
    for (int c = 0; c < 2; c++) {
        const float* pc = pm + (size_t)(n * 2 + c) * HWP;
        const float* wc = wt + (size_t)(o * 2 + c) * 9;
        #pragma unroll
        for (int dy = 0; dy < 3; dy++) {
            int y = i + dy - 1;
            if ((unsigned)y >= (unsigned)HH) continue;
            #pragma unroll
            for (int dx = 0; dx < 3; dx++) {
                int x = j + dx - 1;
                if ((unsigned)x >= (unsigned)WW) continue;
                s = fmaf(wc[dy * 3 + dx], pc[y * WW + x], s);
            }
        }
    }
    out[idx] = fmaxf(s, 0.f);
}

// ---------------------------------------------------------------------------
// deformable bilinear sample
// ---------------------------------------------------------------------------
__global__ void deform_k(const float* __restrict__ feat, const float* __restrict__ pm,
                         float* __restrict__ out) {
    int idx = blockIdx.x * 256 + threadIdx.x;
    if (idx >= N_IMG * 32 * HWP) return;
    int p  = idx % HWP;
    int cg = (idx / HWP) & 31;
    int n  = idx / (32 * HWP);
    int i = p / WW, j = p - (p / WW) * WW;

    float dy = pm[(size_t)(n * 2 + 0) * HWP + p];
    float dx = pm[(size_t)(n * 2 + 1) * HWP + p];
    float gy = (float)i + dy, gx = (float)j + dx;
    float fy = floorf(gy), fx = floorf(gx);
    float ty = gy - fy, tx = gx - fx;
    int y0 = (int)fy, x0 = (int)fx;
    int y1 = y0 + 1, x1 = x0 + 1;
    bool vy0 = (unsigned)y0 < (unsigned)HH, vy1 = (unsigned)y1 < (unsigned)HH;
    bool vx0 = (unsigned)x0 < (unsigned)WW, vx1 = (unsigned)x1 < (unsigned)WW;
    float w00 = (vy0 && vx0) ? (1.f - ty) * (1.f - tx) : 0.f;
    float w01 = (vy0 && vx1) ? (1.f - ty) * tx         : 0.f;
    float w10 = (vy1 && vx0) ? ty * (1.f - tx)         : 0.f;
    float w11 = (vy1 && vx1) ? ty * tx                 : 0.f;
    int y0c = min(max(y0, 0), HH - 1), y1c = min(max(y1, 0), HH - 1);
    int x0c = min(max(x0, 0), WW - 1), x1c = min(max(x1, 0), WW - 1);
    int i00 = y0c * WW + x0c, i01 = y0c * WW + x1c;
    int i10 = y1c * WW + x0c, i11 = y1c * WW + x1c;

    const float* f = feat + ((size_t)(n / 3) * CH + cg * 8) * HWP;
    float* o = out + ((size_t)n * CH + cg * 8) * HWP + p;
    #pragma unroll
    for (int c = 0; c < 8; c++) {
        const float* fc = f + (size_t)c * HWP;
        o[(size_t)c * HWP] = w00 * fc[i00] + w01 * fc[i01] + w10 * fc[i10] + w11 * fc[i11];
    }
}

// ---------------------------------------------------------------------------
// prep_xt: fp32 [img][ic][3136] -> padded pixel-major bf16 hi/lo [img][3248][256]
// ---------------------------------------------------------------------------
__global__ void prep_xt_k(const float* __restrict__ in,
                          __nv_bfloat16* __restrict__ xh, __nv_bfloat16* __restrict__ xl) {
    int idx = blockIdx.x * 256 + threadIdx.x;
    if (idx >= N_IMG * 32 * HWP) return;
    int px  = idx % HWP;
    int icg = (idx / HWP) & 31;
    int img = idx / (32 * HWP);
    int r = px / WW, c = px - r * WW;

    __nv_bfloat16 h[8], l[8];
    #pragma unroll
    for (int k = 0; k < 8; k++) {
        float v = in[((size_t)img * CH + icg * 8 + k) * HWP + px];
        __nv_bfloat16 hv = __float2bfloat16_rn(v);
        h[k] = hv;
        l[k] = __float2bfloat16_rn(v - __bfloat162float(hv));
    }
    size_t dst = ((size_t)img * PHWP + r * PW + c + 1) * CH + icg * 8;
    *(uint4*)(xh + dst) = *(uint4*)h;
    *(uint4*)(xl + dst) = *(uint4*)l;
    uint4 z = {0, 0, 0, 0};
    if (c == 0) {
        size_t d0 = ((size_t)img * PHWP + r * PW + 0) * CH + icg * 8;
        *(uint4*)(xh + d0) = z;  *(uint4*)(xl + d0) = z;
    }
    if (c == WW - 1) {
        size_t d1 = ((size_t)img * PHWP + r * PW + 57) * CH + icg * 8;
        *(uint4*)(xh + d1) = z;  *(uint4*)(xl + d1) = z;
    }
}

// ---------------------------------------------------------------------------
// weight prep: OIHW fp32 -> [tap][oc][ic] bf16 hi/lo
// ---------------------------------------------------------------------------
__global__ void prep_w3_k(const float* __restrict__ w,
                          __nv_bfloat16* __restrict__ wh, __nv_bfloat16* __restrict__ wl) {
    int idx = blockIdx.x * 256 + threadIdx.x;
    if (idx >= 9 * CH * CH) return;
    int tap = idx / (CH * CH);
    int rem = idx - tap * (CH * CH);
    int oc = rem >> 8, ic = rem & 255;
    float v = w[(size_t)(oc * CH + ic) * 9 + tap];
    __nv_bfloat16 hv = __float2bfloat16_rn(v);
    wh[idx] = hv;
    wl[idx] = __float2bfloat16_rn(v - __bfloat162float(hv));
}
__global__ void prep_w1_k(const float* __restrict__ w,
                          __nv_bfloat16* __restrict__ wh, __nv_bfloat16* __restrict__ wl) {
    int idx = blockIdx.x * 256 + threadIdx.x;
    if (idx >= CH * CH) return;
    float v = w[idx];
    __nv_bfloat16 hv = __float2bfloat16_rn(v);
    wh[idx] = hv;
    wl[idx] = __float2bfloat16_rn(v - __bfloat162float(hv));
}

// ---------------------------------------------------------------------------
// HMMA implicit-GEMM conv: D[128 oc, 112 px] = sum_{tap,ic} W * X_shift
//   8 warps: warp (wm,wn) = (w&3, w>>2) -> 32 oc x 56 px (2x7 m16n8k16 frags)
//   split-bf16: Ah*Bh + Ah*Bl + Al*Bh, fp32 accumulators in registers.
//   grid = (28 px-tiles, 2 oc-tiles, 24 imgs), 256 threads.
// ---------------------------------------------------------------------------
__global__ __launch_bounds__(256, 2)
void gemm_conv_k(const __nv_bfloat16* __restrict__ xt_hi, const __nv_bfloat16* __restrict__ xt_lo,
                 const __nv_bfloat16* __restrict__ wA_hi, const __nv_bfloat16* __restrict__ wA_lo,
                 const float* __restrict__ bias, const float* __restrict__ extra,
                 float* __restrict__ out, int ntaps, int relu, int has_extra) {
    extern __shared__ char smem[];
    const uint32_t sb = smem_u32(smem);
    const int tid = threadIdx.x;
    const int warp = tid >> 5, lane = tid & 31;
    const int wm = warp & 3, wn = warp >> 2;
    const int pxb = blockIdx.x, ocb = blockIdx.y, img = blockIdx.z;
    const int p0 = pxb * 112;              // 2 image rows of 56
    const int r0 = p0 / WW;

    const __nv_bfloat16* xh = xt_hi + (size_t)img * PHWP * CH;
    const __nv_bfloat16* xl = xt_lo + (size_t)img * PHWP * CH;

    float acc[2][7][4];
    #pragma unroll
    for (int mf = 0; mf < 2; mf++)
        #pragma unroll
        for (int nf = 0; nf < 7; nf++)
            #pragma unroll
            for (int k = 0; k < 4; k++) acc[mf][nf][k] = 0.f;

    // per-lane ldmatrix base addresses
    const uint32_t aRow = wm * 32 + (lane & 15);
    const uint32_t aOff = (uint32_t)(lane >> 4) * 16;
    const uint32_t aHi = sb + SM_AHI + aRow * RS + aOff;
    const uint32_t aLo = sb + SM_ALO + aRow * RS + aOff;
    const uint32_t bRow = wn * 56 + (lane & 7);
    const uint32_t bOff = (uint32_t)((lane >> 3) & 1) * 16;
    const uint32_t bHi = sb + SM_BHI + bRow * RS + bOff;
    const uint32_t bLo = sb + SM_BLO + bRow * RS + bOff;

    for (int ic0 = 0; ic0 < CH; ic0 += 64) {
        for (int t = 0; t < ntaps; t++) {
            const int dy = (ntaps == 9) ? (t / 3 - 1) : 0;
            const int dx = (ntaps == 9) ? (t % 3 - 1) : 0;
            __syncthreads();
            // --- stage A: 128 oc x 64 ic (K-major, 144B stride) hi+lo ---
            #pragma unroll
            for (int i = 0; i < 4; i++) {
                int idx = tid + i * 256;                  // 1024 uint4
                int row = idx >> 3, seg = idx & 7;
                size_t g = ((size_t)(t * CH + ocb * 128 + row)) * CH + ic0 + seg * 8;
                uint32_t so = (uint32_t)row * RS + seg * 16;
                *(uint4*)(smem + SM_AHI + so) = *(const uint4*)(wA_hi + g);
                *(uint4*)(smem + SM_ALO + so) = *(const uint4*)(wA_lo + g);
            }
            // --- stage B: 112 px x 64 ic, tap-shifted with row-validity mask ---
            for (int idx = tid; idx < 896; idx += 256) {
                int n = idx >> 3, seg = idx & 7;
                int q = n / WW, c = n - q * WW;
                int rr = r0 + q + dy;
                uint32_t so = (uint32_t)n * RS + seg * 16;
                uint4 vh = {0, 0, 0, 0}, vl = {0, 0, 0, 0};
                if ((unsigned)rr < (unsigned)HH) {
                    size_t g = ((size_t)rr * PW + c + dx + 1) * CH + ic0 + seg * 8;
                    vh = *(const uint4*)(xh + g);
                    vl = *(const uint4*)(xl + g);
                }
                *(uint4*)(smem + SM_BHI + so) = vh;
                *(uint4*)(smem + SM_BLO + so) = vl;
            }
            __syncthreads();

            // --- compute: 4 k-steps of 16 ---
            #pragma unroll
            for (int ks = 0; ks < 4; ks++) {
                uint32_t ah[2][4], al[2][4];
                #pragma unroll
                for (int mf = 0; mf < 2; mf++) {
                    ldsm_x4(ah[mf], aHi + mf * 16 * RS + ks * 32);
                    ldsm_x4(al[mf], aLo + mf * 16 * RS + ks * 32);
                }
                #pragma unroll
                for (int nf = 0; nf < 7; nf++) {
                    uint32_t bh[2], bl[2];
                    ldsm_x2(bh, bHi + nf * 8 * RS + ks * 32);
                    ldsm_x2(bl, bLo + nf * 8 * RS + ks * 32);
                    #pragma unroll
                    for (int mf = 0; mf < 2; mf++) {
                        mma16816(acc[mf][nf], ah[mf], bh);
                        mma16816(acc[mf][nf], ah[mf], bl);
                        mma16816(acc[mf][nf], al[mf], bh);
                    }
                }
            }
        }
    }

    // ---- epilogue: registers -> gmem with bias/relu/residual ----
    const int qr = lane >> 2, qc = 2 * (lane & 3);
    #pragma unroll
    for (int mf = 0; mf < 2; mf++) {
        #pragma unroll
        for (int half = 0; half < 2; half++) {
            int oc = ocb * 128 + wm * 32 + mf * 16 + qr + half * 8;
            float b = bias[oc];
            size_t obase = ((size_t)img * CH + oc) * HWP + p0 + wn * 56;
            #pragma unroll
            for (int nf = 0; nf < 7; nf++) {
                size_t o = obase + nf * 8 + qc;
                float v0 = acc[mf][nf][half * 2 + 0] + b;
                float v1 = acc[mf][nf][half * 2 + 1] + b;
                if (relu) { v0 = fmaxf(v0, 0.f); v1 = fmaxf(v1, 0.f); }
                if (has_extra) {
                    float2 e = *(const float2*)(extra + o);
                    v0 += e.x; v1 += e.y;
                }
                float2 r; r.x = v0; r.y = v1;
                *(float2*)(out + o) = r;
            }
        }
    }
}

// ---------------------------------------------------------------------------
// spatial mean pool
// ---------------------------------------------------------------------------
__global__ void pool_k(const float* __restrict__ p2d, float* __restrict__ pooled) {
    int nc = blockIdx.x;
    const float* src = p2d + (size_t)nc * HWP;
    float s = 0.f;
    for (int i = threadIdx.x; i < HWP; i += 256) s += src[i];
    #pragma unroll
    for (int o = 16; o > 0; o >>= 1) s += __shfl_xor_sync(0xffffffffu, s, o);
    __shared__ float sm[8];
    if ((threadIdx.x & 31) == 0) sm[threadIdx.x >> 5] = s;
    __syncthreads();
    if (threadIdx.x < 8) {
        s = sm[threadIdx.x];
        #pragma unroll
        for (int o = 4; o > 0; o >>= 1) s += __shfl_xor_sync(0xffu, s, o);
        if (threadIdx.x == 0) pooled[nc] = s * (1.f / (float)HWP);
    }
}

// ---------------------------------------------------------------------------
extern "C" void kernel_launch(void* const* d_in, const int* in_sizes, int n_in,
                              void* d_out, int out_size) {
    const float* i_features = (const float*)d_in[1];
    const float* p_motions  = (const float*)d_in[2];
    const float* dw  = (const float*)d_in[3];
    const float* db  = (const float*)d_in[4];
    const float* mw1 = (const float*)d_in[5];
    const float* mb1 = (const float*)d_in[6];
    const float* mw2 = (const float*)d_in[7];
    const float* mb2 = (const float*)d_in[8];
    const float* mw3 = (const float*)d_in[9];
    const float* mb3 = (const float*)d_in[10];
    const float* ew1 = (const float*)d_in[11];
    const float* eb1 = (const float*)d_in[12];
    const float* ew2 = (const float*)d_in[13];
    const float* eb2 = (const float*)d_in[14];
    const float* ew3 = (const float*)d_in[15];
    const float* eb3 = (const float*)d_in[16];
    const float* ew4 = (const float*)d_in[17];
    const float* eb4 = (const float*)d_in[18];
    float* out = (float*)d_out;

    float *pm, *bA, *bB, *bC;
    __nv_bfloat16 *xh, *xl, *wh, *wl;
    cudaGetSymbolAddress((void**)&pm, g_pm);
    cudaGetSymbolAddress((void**)&bA, g_bufA);
    cudaGetSymbolAddress((void**)&bB, g_bufB);
    cudaGetSymbolAddress((void**)&bC, g_bufC);
    cudaGetSymbolAddress((void**)&xh, g_xt_hi);
    cudaGetSymbolAddress((void**)&xl, g_xt_lo);
    cudaGetSymbolAddress((void**)&wh, g_wA_hi);
    cudaGetSymbolAddress((void**)&wl, g_wA_lo);

    cudaFuncSetAttribute(gemm_conv_k, cudaFuncAttributeMaxDynamicSharedMemorySize, SM_TOT);

    float* pooled = out;
    float* p2d    = out + 6144;

    const dim3 gg(28, 2, N_IMG);
    const int PB = cdiv(N_IMG * 32 * HWP, 256);
    const int W3 = cdiv(9 * CH * CH, 256);
    const int W1 = cdiv(CH * CH, 256);

    downsample_k<<<cdiv(48 * HWP, 256), 256>>>(p_motions, pm);
    conv_first_k<<<cdiv(N_IMG * CH * HWP, 256), 256>>>(pm, ew1, eb1, bA);

    // emb chain (tensor): A -> B -> A -> C
    prep_w3_k<<<W3, 256>>>(ew2, wh, wl);
    prep_xt_k<<<PB, 256>>>(bA, xh, xl);
    gemm_conv_k<<<gg, 256, SM_TOT>>>(xh, xl, wh, wl, eb2, nullptr, bB, 9, 1, 0);

    prep_w3_k<<<W3, 256>>>(ew3, wh, wl);
    prep_xt_k<<<PB, 256>>>(bB, xh, xl);
    gemm_conv_k<<<gg, 256, SM_TOT>>>(xh, xl, wh, wl, eb3, nullptr, bA, 9, 1, 0);

    prep_w3_k<<<W3, 256>>>(ew4, wh, wl);
    prep_xt_k<<<PB, 256>>>(bA, xh, xl);
    gemm_conv_k<<<gg, 256, SM_TOT>>>(xh, xl, wh, wl, eb4, nullptr, bC, 9, 1, 0);

    // deform sample -> A; 1x1 (tensor, 1 tap, no relu) -> B
    deform_k<<<cdiv(N_IMG * 32 * HWP, 256), 256>>>(i_features, pm, bA);
    prep_w1_k<<<W1, 256>>>(dw, wh, wl);
    prep_xt_k<<<PB, 256>>>(bA, xh, xl);
    gemm_conv_k<<<gg, 256, SM_TOT>>>(xh, xl, wh, wl, db, nullptr, bB, 1, 0, 0);

    // pf chain: B -> A -> B -> p2d(+emb)
    prep_w3_k<<<W3, 256>>>(mw1, wh, wl);
    prep_xt_k<<<PB, 256>>>(bB, xh, xl);
    gemm_conv_k<<<gg, 256, SM_TOT>>>(xh, xl, wh, wl, mb1, nullptr, bA, 9, 1, 0);

    prep_w3_k<<<W3, 256>>>(mw2, wh, wl);
    prep_xt_k<<<PB, 256>>>(bA, xh, xl);
    gemm_conv_k<<<gg, 256, SM_TOT>>>(xh, xl, wh, wl, mb2, nullptr, bB, 9, 1, 0);

    prep_w3_k<<<W3, 256>>>(mw3, wh, wl);
    prep_xt_k<<<PB, 256>>>(bB, xh, xl);
    gemm_conv_k<<<gg, 256, SM_TOT>>>(xh, xl, wh, wl, mb3, bC, p2d, 9, 1, 1);

    pool_k<<<N_IMG * CH, 256>>>(p2d, pooled);
}

// round 6
// speedup vs baseline: 3.2684x; 1.2542x over previous
#include <cuda_runtime.h>
#include <cuda_bf16.h>
#include <cstdint>

// ---------------------------------------------------------------------------
// UpsampleUpdatingModel2 — split-bf16 implicit-GEMM convs on mma.sync (HMMA)
// R5->R6: B-tile reuse across dx (+-1 row offset), cp.async double-buffered A.
// ---------------------------------------------------------------------------

#define N_IMG 24
#define CH    256
#define HH    56
#define WW    56
#define HWP   3136
#define PW    58          // padded row width (1 zero col each side)
#define PHWP  3248        // 56*58 padded pixels per image

__device__ __align__(128) float g_pm  [N_IMG * 2 * HWP];
__device__ __align__(128) float g_bufA[N_IMG * CH * HWP];
__device__ __align__(128) float g_bufB[N_IMG * CH * HWP];
__device__ __align__(128) float g_bufC[N_IMG * CH * HWP];
__device__ __align__(128) __nv_bfloat16 g_xt_hi[N_IMG * PHWP * CH];
__device__ __align__(128) __nv_bfloat16 g_xt_lo[N_IMG * PHWP * CH];
__device__ __align__(128) __nv_bfloat16 g_wA_hi[9 * CH * CH];   // [tap][oc][ic]
__device__ __align__(128) __nv_bfloat16 g_wA_lo[9 * CH * CH];

static inline int cdiv(int a, int b) { return (a + b - 1) / b; }

// ------------------------------ PTX helpers --------------------------------
__device__ __forceinline__ uint32_t smem_u32(const void* p) {
    uint32_t a;
    asm("{ .reg .u64 t; cvta.to.shared.u64 t, %1; cvt.u32.u64 %0, t; }" : "=r"(a) : "l"(p));
    return a;
}
__device__ __forceinline__ void ldsm_x4(uint32_t* r, uint32_t addr) {
    asm volatile("ldmatrix.sync.aligned.m8n8.x4.shared.b16 {%0,%1,%2,%3}, [%4];"
                 : "=r"(r[0]), "=r"(r[1]), "=r"(r[2]), "=r"(r[3]) : "r"(addr));
}
__device__ __forceinline__ void ldsm_x2(uint32_t* r, uint32_t addr) {
    asm volatile("ldmatrix.sync.aligned.m8n8.x2.shared.b16 {%0,%1}, [%2];"
                 : "=r"(r[0]), "=r"(r[1]) : "r"(addr));
}
__device__ __forceinline__ void mma16816(float* d, const uint32_t* a, const uint32_t* b) {
    asm volatile(
        "mma.sync.aligned.m16n8k16.row.col.f32.bf16.bf16.f32 "
        "{%0,%1,%2,%3}, {%4,%5,%6,%7}, {%8,%9}, {%0,%1,%2,%3};"
        : "+f"(d[0]), "+f"(d[1]), "+f"(d[2]), "+f"(d[3])
        : "r"(a[0]), "r"(a[1]), "r"(a[2]), "r"(a[3]), "r"(b[0]), "r"(b[1]));
}
__device__ __forceinline__ void cpa16(uint32_t dst, const void* src, bool valid) {
    asm volatile("cp.async.cg.shared.global [%0], [%1], 16, %2;"
                 :: "r"(dst), "l"(src), "r"(valid ? 16u : 0u));
}
#define CPA_COMMIT() asm volatile("cp.async.commit_group;")
template <int N>
__device__ __forceinline__ void cpa_wait() {
    asm volatile("cp.async.wait_group %0;" :: "n"(N));
}

// SMEM layout: K-major tiles, 64 ic per stage, row stride 144B (ldmatrix
// conflict-free). A double-buffered (hi then lo per buf), B single (hi, lo).
#define RS     144
#define A_BUF_BYTES (2 * 128 * RS)          // 36864 (hi+lo)
#define SM_A0  0
#define SM_A1  (SM_A0 + A_BUF_BYTES)
#define SM_B   (SM_A1 + A_BUF_BYTES)        // 116 rows hi + 116 rows lo
#define SM_TOT (SM_B + 2 * 116 * RS)        // 107136

// ---------------------------------------------------------------------------
__global__ void downsample_k(const float* __restrict__ src, float* __restrict__ dst) {
    int idx = blockIdx.x * 256 + threadIdx.x;
    if (idx >= 48 * HWP) return;
    int nc = idx / HWP, p = idx - nc * HWP;
    int i = p / WW, j = p - i * WW;
    const float* s = src + (size_t)nc * 112 * 112;
    int base = (2 * i) * 112 + 2 * j;
    dst[idx] = (s[base] + s[base + 1] + s[base + 112] + s[base + 113]) * 0.0625f;
}

// ---------------------------------------------------------------------------
__global__ void conv_first_k(const float* __restrict__ pm, const float* __restrict__ wt,
                             const float* __restrict__ bias, float* __restrict__ out) {
    int idx = blockIdx.x * 256 + threadIdx.x;
    if (idx >= N_IMG * CH * HWP) return;
    int p = idx % HWP;
    int o = (idx / HWP) & (CH - 1);
    int n = idx / (CH * HWP);
    int i = p / WW, j = p - (p / WW) * WW;
    float s = bias[o];
    #pragma unroll
    for (int c = 0; c < 2; c++) {
        const float* pc = pm + (size_t)(n * 2 + c) * HWP;
        const float* wc = wt + (size_t)(o * 2 + c) * 9;
        #pragma unroll
        for (int dy = 0; dy < 3; dy++) {
            int y = i + dy - 1;
            if ((unsigned)y >= (unsigned)HH) continue;
            #pragma unroll
            for (int dx = 0; dx < 3; dx++) {
                int x = j + dx - 1;
                if ((unsigned)x >= (unsigned)WW) continue;
                s = fmaf(wc[dy * 3 + dx], pc[y * WW + x], s);
            }
        }
    }
    out[idx] = fmaxf(s, 0.f);
}

// ---------------------------------------------------------------------------
__global__ void deform_k(const float* __restrict__ feat, const float* __restrict__ pm,
                         float* __restrict__ out) {
    int idx = blockIdx.x * 256 + threadIdx.x;
    if (idx >= N_IMG * 32 * HWP) return;
    int p  = idx % HWP;
    int cg = (idx / HWP) & 31;
    int n  = idx / (32 * HWP);
    int i = p / WW, j = p - (p / WW) * WW;

    float dy = pm[(size_t)(n * 2 + 0) * HWP + p];
    float dx = pm[(size_t)(n * 2 + 1) * HWP + p];
    float gy = (float)i + dy, gx = (float)j + dx;
    float fy = floorf(gy), fx = floorf(gx);
    float ty = gy - fy, tx = gx - fx;
    int y0 = (int)fy, x0 = (int)fx;
    int y1 = y0 + 1, x1 = x0 + 1;
    bool vy0 = (unsigned)y0 < (unsigned)HH, vy1 = (unsigned)y1 < (unsigned)HH;
    bool vx0 = (unsigned)x0 < (unsigned)WW, vx1 = (unsigned)x1 < (unsigned)WW;
    float w00 = (vy0 && vx0) ? (1.f - ty) * (1.f - tx) : 0.f;
    float w01 = (vy0 && vx1) ? (1.f - ty) * tx         : 0.f;
    float w10 = (vy1 && vx0) ? ty * (1.f - tx)         : 0.f;
    float w11 = (vy1 && vx1) ? ty * tx                 : 0.f;
    int y0c = min(max(y0, 0), HH - 1), y1c = min(max(y1, 0), HH - 1);
    int x0c = min(max(x0, 0), WW - 1), x1c = min(max(x1, 0), WW - 1);
    int i00 = y0c * WW + x0c, i01 = y0c * WW + x1c;
    int i10 = y1c * WW + x0c, i11 = y1c * WW + x1c;

    const float* f = feat + ((size_t)(n / 3) * CH + cg * 8) * HWP;
    float* o = out + ((size_t)n * CH + cg * 8) * HWP + p;
    #pragma unroll
    for (int c = 0; c < 8; c++) {
        const float* fc = f + (size_t)c * HWP;
        o[(size_t)c * HWP] = w00 * fc[i00] + w01 * fc[i01] + w10 * fc[i10] + w11 * fc[i11];
    }
}

// ---------------------------------------------------------------------------
__global__ void prep_xt_k(const float* __restrict__ in,
                          __nv_bfloat16* __restrict__ xh, __nv_bfloat16* __restrict__ xl) {
    int idx = blockIdx.x * 256 + threadIdx.x;
    if (idx >= N_IMG * 32 * HWP) return;
    int px  = idx % HWP;
    int icg = (idx / HWP) & 31;
    int img = idx / (32 * HWP);
    int r = px / WW, c = px - r * WW;

    __nv_bfloat16 h[8], l[8];
    #pragma unroll
    for (int k = 0; k < 8; k++) {
        float v = in[((size_t)img * CH + icg * 8 + k) * HWP + px];
        __nv_bfloat16 hv = __float2bfloat16_rn(v);
        h[k] = hv;
        l[k] = __float2bfloat16_rn(v - __bfloat162float(hv));
    }
    size_t dst = ((size_t)img * PHWP + r * PW + c + 1) * CH + icg * 8;
    *(uint4*)(xh + dst) = *(uint4*)h;
    *(uint4*)(xl + dst) = *(uint4*)l;
    uint4 z = {0, 0, 0, 0};
    if (c == 0) {
        size_t d0 = ((size_t)img * PHWP + r * PW + 0) * CH + icg * 8;
        *(uint4*)(xh + d0) = z;  *(uint4*)(xl + d0) = z;
    }
    if (c == WW - 1) {
        size_t d1 = ((size_t)img * PHWP + r * PW + 57) * CH + icg * 8;
        *(uint4*)(xh + d1) = z;  *(uint4*)(xl + d1) = z;
    }
}

// ---------------------------------------------------------------------------
__global__ void prep_w3_k(const float* __restrict__ w,
                          __nv_bfloat16* __restrict__ wh, __nv_bfloat16* __restrict__ wl) {
    int idx = blockIdx.x * 256 + threadIdx.x;
    if (idx >= 9 * CH * CH) return;
    int tap = idx / (CH * CH);
    int rem = idx - tap * (CH * CH);
    int oc = rem >> 8, ic = rem & 255;
    float v = w[(size_t)(oc * CH + ic) * 9 + tap];
    __nv_bfloat16 hv = __float2bfloat16_rn(v);
    wh[idx] = hv;
    wl[idx] = __float2bfloat16_rn(v - __bfloat162float(hv));
}
__global__ void prep_w1_k(const float* __restrict__ w,
                          __nv_bfloat16* __restrict__ wh, __nv_bfloat16* __restrict__ wl) {
    int idx = blockIdx.x * 256 + threadIdx.x;
    if (idx >= CH * CH) return;
    float v = w[idx];
    __nv_bfloat16 hv = __float2bfloat16_rn(v);
    wh[idx] = hv;
    wl[idx] = __float2bfloat16_rn(v - __bfloat162float(hv));
}

// ---------------------------------------------------------------------------
// HMMA implicit-GEMM conv with pipelined staging.
//   CTA = 128 oc x 112 px (2 image rows). 8 warps: (wm,wn)=(w&3,w>>2).
//   Per (ic-chunk, dy): stage B once (116 padded pixel-rows incl. halo);
//   dx taps are +-1 row offsets. A double-buffered via cp.async.
// ---------------------------------------------------------------------------
struct Frag { float a[2][7][4]; };

__device__ __forceinline__ void stage_A(uint32_t sb, uint32_t bufoff,
                                        const __nv_bfloat16* wh, const __nv_bfloat16* wl,
                                        int tap, int ocb, int ic0, int tid) {
    #pragma unroll
    for (int i = 0; i < 8; i++) {
        int idx = tid + i * 256;                 // 0..2047
        int half = idx >> 10;
        int r = idx & 1023;
        int row = r >> 3, seg = r & 7;
        size_t g = ((size_t)(tap * CH + ocb * 128 + row)) * CH + ic0 + seg * 8;
        uint32_t dst = sb + bufoff + (uint32_t)half * (128 * RS) + (uint32_t)row * RS + seg * 16;
        cpa16(dst, (half ? wl : wh) + g, true);
    }
}

__device__ __forceinline__ void stage_B(uint32_t sb,
                                        const __nv_bfloat16* xh, const __nv_bfloat16* xl,
                                        int pstart, int tid) {
    #pragma unroll
    for (int i = 0; i < 8; i++) {
        int idx = tid + i * 256;
        if (idx >= 1856) break;                  // 2*116*8 chunks
        int half = idx >= 928;
        int r = idx - half * 928;
        int row = r >> 3, seg = r & 7;
        int p = pstart + row;
        bool valid = (p >= 0) && (p < HH * PW);
        size_t g = (size_t)(valid ? p : 0) * CH + seg * 8;
        uint32_t dst = sb + SM_B + (uint32_t)half * (116 * RS) + (uint32_t)row * RS + seg * 16;
        cpa16(dst, (half ? xl : xh) + g, valid);
    }
}

__device__ __forceinline__ void do_compute(uint32_t sb, uint32_t abuf, int dx,
                                           int wm, int wn, int lane, float acc[2][7][4]) {
    const uint32_t aRow = wm * 32 + (lane & 15);
    const uint32_t aHi = sb + abuf + aRow * RS + (uint32_t)((lane >> 4) & 1) * 16;
    const uint32_t aLo = aHi + 128 * RS;
    const uint32_t bRow = wn * 58 + 1 + dx + (lane & 7);
    const uint32_t bHi = sb + SM_B + bRow * RS + (uint32_t)((lane >> 3) & 1) * 16;
    const uint32_t bLo = bHi + 116 * RS;
    #pragma unroll
    for (int ks = 0; ks < 4; ks++) {
        uint32_t ah[2][4], al[2][4];
        #pragma unroll
        for (int mf = 0; mf < 2; mf++) {
            ldsm_x4(ah[mf], aHi + mf * 16 * RS + ks * 32);
            ldsm_x4(al[mf], aLo + mf * 16 * RS + ks * 32);
        }
        #pragma unroll
        for (int nf = 0; nf < 7; nf++) {
            uint32_t bh[2], bl[2];
            ldsm_x2(bh, bHi + nf * 8 * RS + ks * 32);
            ldsm_x2(bl, bLo + nf * 8 * RS + ks * 32);
            #pragma unroll
            for (int mf = 0; mf < 2; mf++) {
                float* d = &acc[mf][nf][0];
                mma16816(d, ah[mf], bh);
                mma16816(d, ah[mf], bl);
                mma16816(d, al[mf], bh);
            }
        }
    }
}

__global__ __launch_bounds__(256, 2)
void gemm_conv_k(const __nv_bfloat16* __restrict__ xt_hi, const __nv_bfloat16* __restrict__ xt_lo,
                 const __nv_bfloat16* __restrict__ wA_hi, const __nv_bfloat16* __restrict__ wA_lo,
                 const float* __restrict__ bias, const float* __restrict__ extra,
                 float* __restrict__ out, int ntaps, int relu, int has_extra) {
    extern __shared__ char smem[];
    const uint32_t sb = smem_u32(smem);
    const int tid = threadIdx.x;
    const int warp = tid >> 5, lane = tid & 31;
    const int wm = warp & 3, wn = warp >> 2;
    const int pxb = blockIdx.x, ocb = blockIdx.y, img = blockIdx.z;
    const int p0 = pxb * 112;
    const int r0 = p0 / WW;                  // 2 image rows per CTA

    const __nv_bfloat16* xh = xt_hi + (size_t)img * PHWP * CH;
    const __nv_bfloat16* xl = xt_lo + (size_t)img * PHWP * CH;

    float acc[2][7][4];
    #pragma unroll
    for (int mf = 0; mf < 2; mf++)
        #pragma unroll
        for (int nf = 0; nf < 7; nf++)
            #pragma unroll
            for (int k = 0; k < 4; k++) acc[mf][nf][k] = 0.f;

    if (ntaps == 9) {
        for (int ic0 = 0; ic0 < CH; ic0 += 64) {
            #pragma unroll
            for (int dy3 = 0; dy3 < 3; dy3++) {
                const int dy = dy3 - 1;
                __syncthreads();                                   // bufs free
                stage_B(sb, xh + ic0, xl + ic0, (r0 + dy) * PW, tid);
                stage_A(sb, SM_A0, wA_hi, wA_lo, dy3 * 3 + 0, ocb, ic0, tid);
                CPA_COMMIT();                                      // G: {B, A(dx=-1)}
                stage_A(sb, SM_A1, wA_hi, wA_lo, dy3 * 3 + 1, ocb, ic0, tid);
                CPA_COMMIT();                                      // G: {A(dx=0)}
                cpa_wait<1>();  __syncthreads();                   // B + A0 ready
                do_compute(sb, SM_A0, -1, wm, wn, lane, acc);
                __syncthreads();                                   // A0 buf free
                stage_A(sb, SM_A0, wA_hi, wA_lo, dy3 * 3 + 2, ocb, ic0, tid);
                CPA_COMMIT();                                      // G: {A(dx=+1)}
                cpa_wait<1>();  __syncthreads();                   // A1 ready
                do_compute(sb, SM_A1, 0, wm, wn, lane, acc);
                cpa_wait<0>();  __syncthreads();                   // A2 ready
                do_compute(sb, SM_A0, +1, wm, wn, lane, acc);
            }
        }
    } else {
        for (int ic0 = 0; ic0 < CH; ic0 += 64) {
            __syncthreads();
            stage_B(sb, xh + ic0, xl + ic0, r0 * PW, tid);
            stage_A(sb, SM_A0, wA_hi, wA_lo, 0, ocb, ic0, tid);
            CPA_COMMIT();
            cpa_wait<0>();  __syncthreads();
            do_compute(sb, SM_A0, 0, wm, wn, lane, acc);
        }
    }

    // ---- epilogue ----
    const int qr = lane >> 2, qc = 2 * (lane & 3);
    #pragma unroll
    for (int mf = 0; mf < 2; mf++) {
        #pragma unroll
        for (int half = 0; half < 2; half++) {
            int oc = ocb * 128 + wm * 32 + mf * 16 + qr + half * 8;
            float b = bias[oc];
            size_t obase = ((size_t)img * CH + oc) * HWP + p0 + wn * 56;
            #pragma unroll
            for (int nf = 0; nf < 7; nf++) {
                size_t o = obase + nf * 8 + qc;
                float v0 = acc[mf][nf][half * 2 + 0] + b;
                float v1 = acc[mf][nf][half * 2 + 1] + b;
                if (relu) { v0 = fmaxf(v0, 0.f); v1 = fmaxf(v1, 0.f); }
                if (has_extra) {
                    float2 e = *(const float2*)(extra + o);
                    v0 += e.x; v1 += e.y;
                }
                float2 r; r.x = v0; r.y = v1;
                *(float2*)(out + o) = r;
            }
        }
    }
}

// ---------------------------------------------------------------------------
__global__ void pool_k(const float* __restrict__ p2d, float* __restrict__ pooled) {
    int nc = blockIdx.x;
    const float* src = p2d + (size_t)nc * HWP;
    float s = 0.f;
    for (int i = threadIdx.x; i < HWP; i += 256) s += src[i];
    #pragma unroll
    for (int o = 16; o > 0; o >>= 1) s += __shfl_xor_sync(0xffffffffu, s, o);
    __shared__ float sm[8];
    if ((threadIdx.x & 31) == 0) sm[threadIdx.x >> 5] = s;
    __syncthreads();
    if (threadIdx.x < 8) {
        s = sm[threadIdx.x];
        #pragma unroll
        for (int o = 4; o > 0; o >>= 1) s += __shfl_xor_sync(0xffu, s, o);
        if (threadIdx.x == 0) pooled[nc] = s * (1.f / (float)HWP);
    }
}

// ---------------------------------------------------------------------------
extern "C" void kernel_launch(void* const* d_in, const int* in_sizes, int n_in,
                              void* d_out, int out_size) {
    const float* i_features = (const float*)d_in[1];
    const float* p_motions  = (const float*)d_in[2];
    const float* dw  = (const float*)d_in[3];
    const float* db  = (const float*)d_in[4];
    const float* mw1 = (const float*)d_in[5];
    const float* mb1 = (const float*)d_in[6];
    const float* mw2 = (const float*)d_in[7];
    const float* mb2 = (const float*)d_in[8];
    const float* mw3 = (const float*)d_in[9];
    const float* mb3 = (const float*)d_in[10];
    const float* ew1 = (const float*)d_in[11];
    const float* eb1 = (const float*)d_in[12];
    const float* ew2 = (const float*)d_in[13];
    const float* eb2 = (const float*)d_in[14];
    const float* ew3 = (const float*)d_in[15];
    const float* eb3 = (const float*)d_in[16];
    const float* ew4 = (const float*)d_in[17];
    const float* eb4 = (const float*)d_in[18];
    float* out = (float*)d_out;

    float *pm, *bA, *bB, *bC;
    __nv_bfloat16 *xh, *xl, *wh, *wl;
    cudaGetSymbolAddress((void**)&pm, g_pm);
    cudaGetSymbolAddress((void**)&bA, g_bufA);
    cudaGetSymbolAddress((void**)&bB, g_bufB);
    cudaGetSymbolAddress((void**)&bC, g_bufC);
    cudaGetSymbolAddress((void**)&xh, g_xt_hi);
    cudaGetSymbolAddress((void**)&xl, g_xt_lo);
    cudaGetSymbolAddress((void**)&wh, g_wA_hi);
    cudaGetSymbolAddress((void**)&wl, g_wA_lo);

    cudaFuncSetAttribute(gemm_conv_k, cudaFuncAttributeMaxDynamicSharedMemorySize, SM_TOT);

    float* pooled = out;
    float* p2d    = out + 6144;

    const dim3 gg(28, 2, N_IMG);
    const int PB = cdiv(N_IMG * 32 * HWP, 256);
    const int W3 = cdiv(9 * CH * CH, 256);
    const int W1 = cdiv(CH * CH, 256);

    downsample_k<<<cdiv(48 * HWP, 256), 256>>>(p_motions, pm);
    conv_first_k<<<cdiv(N_IMG * CH * HWP, 256), 256>>>(pm, ew1, eb1, bA);

    // emb chain: A -> B -> A -> C
    prep_w3_k<<<W3, 256>>>(ew2, wh, wl);
    prep_xt_k<<<PB, 256>>>(bA, xh, xl);
    gemm_conv_k<<<gg, 256, SM_TOT>>>(xh, xl, wh, wl, eb2, nullptr, bB, 9, 1, 0);

    prep_w3_k<<<W3, 256>>>(ew3, wh, wl);
    prep_xt_k<<<PB, 256>>>(bB, xh, xl);
    gemm_conv_k<<<gg, 256, SM_TOT>>>(xh, xl, wh, wl, eb3, nullptr, bA, 9, 1, 0);

    prep_w3_k<<<W3, 256>>>(ew4, wh, wl);
    prep_xt_k<<<PB, 256>>>(bA, xh, xl);
    gemm_conv_k<<<gg, 256, SM_TOT>>>(xh, xl, wh, wl, eb4, nullptr, bC, 9, 1, 0);

    // deform -> A; 1x1 -> B
    deform_k<<<cdiv(N_IMG * 32 * HWP, 256), 256>>>(i_features, pm, bA);
    prep_w1_k<<<W1, 256>>>(dw, wh, wl);
    prep_xt_k<<<PB, 256>>>(bA, xh, xl);
    gemm_conv_k<<<gg, 256, SM_TOT>>>(xh, xl, wh, wl, db, nullptr, bB, 1, 0, 0);

    // pf chain: B -> A -> B -> p2d(+emb)
    prep_w3_k<<<W3, 256>>>(mw1, wh, wl);
    prep_xt_k<<<PB, 256>>>(bB, xh, xl);
    gemm_conv_k<<<gg, 256, SM_TOT>>>(xh, xl, wh, wl, mb1, nullptr, bA, 9, 1, 0);

    prep_w3_k<<<W3, 256>>>(mw2, wh, wl);
    prep_xt_k<<<PB, 256>>>(bA, xh, xl);
    gemm_conv_k<<<gg, 256, SM_TOT>>>(xh, xl, wh, wl, mb2, nullptr, bB, 9, 1, 0);

    prep_w3_k<<<W3, 256>>>(mw3, wh, wl);
    prep_xt_k<<<PB, 256>>>(bB, xh, xl);
    gemm_conv_k<<<gg, 256, SM_TOT>>>(xh, xl, wh, wl, mb3, bC, p2d, 9, 1, 1);

    pool_k<<<N_IMG * CH, 256>>>(p2d, pooled);
}